// round 16
// baseline (speedup 1.0000x reference)
#include <cuda_runtime.h>
#include <math.h>

#define DD 128
static const int NC = DD * DD * DD;   // cells per layer

// smem per field-row: E (128 floats, plain) + O (65 pair slots = 130 floats,
// O[k] = (v[2k-1], v[2k]) with periodic wrap) + 2 pad. 18 rows (3z x 6y halo).
// ROWF must be a multiple of 4 so float4 row stores stay 16B-aligned.
#define ROWF 260
#define F_STRIDE (18 * ROWF)          // 4680 floats per field
#define SMEM_FLOATS (6 * F_STRIDE)    // 28080 floats = 112320 B
#define FILL_G (6 * 18 * 32)          // float4 granules per phase = 3456

typedef unsigned long long f2;        // packed f32x2

__device__ __forceinline__ f2 pk(float lo, float hi) {
    f2 r; asm("mov.b64 %0,{%1,%2};" : "=l"(r) : "f"(lo), "f"(hi)); return r;
}
__device__ __forceinline__ void up(f2 v, float& lo, float& hi) {
    asm("mov.b64 {%0,%1},%2;" : "=f"(lo), "=f"(hi) : "l"(v));
}
__device__ __forceinline__ f2 fma2(f2 a, f2 b, f2 c) {
    f2 d; asm("fma.rn.f32x2 %0,%1,%2,%3;" : "=l"(d) : "l"(a), "l"(b), "l"(c)); return d;
}
__device__ __forceinline__ f2 mul2(f2 a, f2 b) {
    f2 d; asm("mul.rn.f32x2 %0,%1,%2;" : "=l"(d) : "l"(a), "l"(b)); return d;
}
__device__ __forceinline__ float rsqrt_fast(float x) {
    float y; asm("rsqrt.approx.f32 %0, %1;" : "=f"(y) : "f"(x)); return y;
}

__device__ __forceinline__ float boundary_force(float p, float v, float mv, float ETAf) {
    float lo = (p > 0.1f && p < 0.15f) ? mv : 0.0f;
    float hi = (p > 12.65f) ? mv : 0.0f;
    float fb = 6.0e6f * lo * (0.15f - p);
    fb -= 6.0e6f * hi * (((p - 12.8f) + 0.1f) + 0.05f);
    fb -= ETAf * v * lo;
    fb -= ETAf * v * hi;
    return fb;
}

struct Consts { f2 NEG1, EPS2, KN2, NKPS2, ETA2; };

// One packed interaction: 2 adjacent cells (packed centers C[0..5]) vs one
// window f2 per field — operands arrive pre-paired from aligned LDS.64.
__device__ __forceinline__ void interact(
    const f2* __restrict__ C,
    f2 WX, f2 WY, f2 WZ, f2 WVX, f2 WVY, f2 WVZ,
    f2& FX, f2& FY, f2& FZ, const Consts& K)
{
    f2 dx2 = fma2(WX, K.NEG1, C[0]);
    f2 dy2 = fma2(WY, K.NEG1, C[1]);
    f2 dz2 = fma2(WZ, K.NEG1, C[2]);
    f2 s2  = fma2(dz2, dz2, K.EPS2);     // +1e-8 floor folded in
    s2 = fma2(dy2, dy2, s2);
    s2 = fma2(dx2, dx2, s2);
    float s0, s1; up(s2, s0, s1);
    float r0 = rsqrt_fast(s0);
    float r1 = rsqrt_fast(s1);
    r0 = (s0 < 0.01f) ? r0 : 0.0f;       // contact gate folded into r
    r1 = (s1 < 0.01f) ? r1 : 0.0f;
    f2 rg = pk(r0, r1);
    f2 dist2 = mul2(s2, rg);             // = sqrt(s2) where gated-in, else 0
    f2 dvx2 = fma2(WVX, K.NEG1, C[3]);
    f2 dvy2 = fma2(WVY, K.NEG1, C[4]);
    f2 dvz2 = fma2(WVZ, K.NEG1, C[5]);
    f2 dot2 = mul2(dvz2, dz2);
    dot2 = fma2(dvy2, dy2, dot2);
    dot2 = fma2(dvx2, dx2, dot2);
    f2 q2 = mul2(dot2, rg);              // dvn/dc (dc clamp automatic: r<=1e4)
    f2 t2 = fma2(K.KN2, dist2, K.NKPS2); // KN*(dist-PS)
    t2 = fma2(K.ETA2, q2, t2);
    f2 coef2 = mul2(t2, rg);             // zero where gated-out
    FX = fma2(coef2, dx2, FX);
    FY = fma2(coef2, dy2, FY);
    FZ = fma2(coef2, dz2, FZ);
}

__global__ void __launch_bounds__(256, 2)
dem_pass(const float* __restrict__ x0, const float* __restrict__ y0, const float* __restrict__ z0,
         const float* __restrict__ x1, const float* __restrict__ y1, const float* __restrict__ z1,
         const float* __restrict__ vxl0, const float* __restrict__ vyl0, const float* __restrict__ vzl0,
         const float* __restrict__ vxl1, const float* __restrict__ vyl1, const float* __restrict__ vzl1,
         const float* __restrict__ cx, const float* __restrict__ cy, const float* __restrict__ cz,
         const float* __restrict__ cvx, const float* __restrict__ cvy, const float* __restrict__ cvz,
         const float* __restrict__ cmask,
         float* __restrict__ ovx, float* __restrict__ ovy, float* __restrict__ ovz,
         float ETAf, float DTPMf, float GPMf)
{
    extern __shared__ float sm[];

    const int tid = threadIdx.x;             // 0..255
    const int q   = tid & 63;                // cell pair index: cells 2q, 2q+1
    const int yl  = tid >> 6;                // 0..3
    const int by4 = blockIdx.x * 4;
    const int zc  = blockIdx.y;
    const int base = (zc * DD + (by4 + yl)) * DD + 2 * q;

    Consts K;
    K.NEG1  = pk(-1.0f, -1.0f);
    K.EPS2  = pk(1e-8f, 1e-8f);
    K.KN2   = pk(6.0e6f, 6.0e6f);
    K.NKPS2 = pk(-600000.0f, -600000.0f);
    K.ETA2  = pk(ETAf, ETAf);

    // centers (layer n): two adjacent cells packed in f2 lanes
    f2 C[6];
    {
        float2 a;
        a = *reinterpret_cast<const float2*>(cx + base);  C[0] = pk(a.x, a.y);
        a = *reinterpret_cast<const float2*>(cy + base);  C[1] = pk(a.x, a.y);
        a = *reinterpret_cast<const float2*>(cz + base);  C[2] = pk(a.x, a.y);
        a = *reinterpret_cast<const float2*>(cvx + base); C[3] = pk(a.x, a.y);
        a = *reinterpret_cast<const float2*>(cvy + base); C[4] = pk(a.x, a.y);
        a = *reinterpret_cast<const float2*>(cvz + base); C[5] = pk(a.x, a.y);
    }

    f2 FX = 0, FY = 0, FZ = 0;

    const int eoff = 2 * q;            // E[q] float offset in row
    const int ooff = 128 + 2 * q;      // O[q] float offset in row

#pragma unroll
    for (int m = 0; m < 2; ++m) {
        const float* Ps[6];
        Ps[0] = m ? x1 : x0;   Ps[1] = m ? y1 : y0;   Ps[2] = m ? z1 : z0;
        Ps[3] = m ? vxl1 : vxl0; Ps[4] = m ? vyl1 : vyl0; Ps[5] = m ? vzl1 : vzl0;

        if (m) __syncthreads();   // protect previous phase's reads before overwrite

        // fill: E = plain row; O = 4B-rotated pair copy (wrap baked in)
        for (int g = tid; g < FILL_G; g += 256) {
            int f = g / 576, rem = g - f * 576;
            int r = rem >> 5, j = rem & 31;
            int gz = (zc + r / 6 - 1) & 127;
            int gy = (by4 + r % 6 - 1) & 127;
            float4 F = *reinterpret_cast<const float4*>(Ps[f] + (gz * DD + gy) * DD + 4 * j);
            float* rowp = sm + f * F_STRIDE + r * ROWF;
            *reinterpret_cast<float4*>(rowp + 4 * j) = F;                 // E
            *reinterpret_cast<float2*>(rowp + 128 + 4 * j + 2) = make_float2(F.y, F.z); // O[2j+1]
            rowp[128 + 4 * j + 1] = F.x;                                  // O[2j].hi
            rowp[128 + 4 * j + 4] = F.w;                                  // O[2j+2].lo
            if (j == 0)  rowp[128 + 129] = F.x;                           // O[64].hi = v[0]
            if (j == 31) rowp[128 + 0]   = F.w;                           // O[0].lo = v[127]
        }
        __syncthreads();

        // 9 rows (3z x 3y); per row per field: 3 aligned conflict-free LDS.64
#pragma unroll
        for (int dz = 0; dz < 3; ++dz) {
#pragma unroll
            for (int dy = 0; dy < 3; ++dy) {
                const float* rp = sm + (dz * 6 + (yl + dy)) * ROWF;
                f2 Wm[6], W0[6], Wp[6];
#pragma unroll
                for (int f = 0; f < 6; ++f) {
                    const float* fp = rp + f * F_STRIDE;
                    Wm[f] = *reinterpret_cast<const f2*>(fp + ooff);      // O[q]   -> shift -1
                    W0[f] = *reinterpret_cast<const f2*>(fp + eoff);      // E[q]   -> shift  0
                    Wp[f] = *reinterpret_cast<const f2*>(fp + ooff + 2);  // O[q+1] -> shift +1
                }
                interact(C, Wm[0], Wm[1], Wm[2], Wm[3], Wm[4], Wm[5], FX, FY, FZ, K);
                interact(C, W0[0], W0[1], W0[2], W0[3], W0[4], W0[5], FX, FY, FZ, K);
                interact(C, Wp[0], Wp[1], Wp[2], Wp[3], Wp[4], Wp[5], FX, FY, FZ, K);
            }
        }
    }

    // epilogue: unpack, boundary forces, update, store (2 cells)
    float fxa0, fxa1, fya0, fya1, fza0, fza1;
    up(FX, fxa0, fxa1); up(FY, fya0, fya1); up(FZ, fza0, fza1);

    float xn0, xn1, yn0, yn1, zn0, zn1, vxn0, vxn1, vyn0, vyn1, vzn0, vzn1;
    up(C[0], xn0, xn1); up(C[1], yn0, yn1); up(C[2], zn0, zn1);
    up(C[3], vxn0, vxn1); up(C[4], vyn0, vyn1); up(C[5], vzn0, vzn1);

    const float2 mk2 = *reinterpret_cast<const float2*>(cmask + base);

    float sc0 = DTPMf * mk2.x;
    float ox0_ = vxn0 + sc0 * (boundary_force(xn0, vxn0, mk2.x, ETAf) - fxa0);
    float oy0_ = vyn0 + sc0 * (boundary_force(yn0, vyn0, mk2.x, ETAf) - fya0);
    float oz0_ = vzn0 + sc0 * ((GPMf - fza0) + boundary_force(zn0, vzn0, mk2.x, ETAf));
    float sc1 = DTPMf * mk2.y;
    float ox1_ = vxn1 + sc1 * (boundary_force(xn1, vxn1, mk2.y, ETAf) - fxa1);
    float oy1_ = vyn1 + sc1 * (boundary_force(yn1, vyn1, mk2.y, ETAf) - fya1);
    float oz1_ = vzn1 + sc1 * ((GPMf - fza1) + boundary_force(zn1, vzn1, mk2.y, ETAf));

    *reinterpret_cast<float2*>(ovx + base) = make_float2(ox0_, ox1_);
    *reinterpret_cast<float2*>(ovy + base) = make_float2(oy0_, oy1_);
    *reinterpret_cast<float2*>(ovz + base) = make_float2(oz0_, oz1_);
}

extern "C" void kernel_launch(void* const* d_in, const int* in_sizes, int n_in,
                              void* d_out, int out_size)
{
    const float* x  = (const float*)d_in[0];
    const float* y  = (const float*)d_in[1];
    const float* z  = (const float*)d_in[2];
    const float* vx = (const float*)d_in[3];
    const float* vy = (const float*)d_in[4];
    const float* vz = (const float*)d_in[5];
    const float* mask = (const float*)d_in[6];
    float* out = (float*)d_out;
    const int N = NC;

    const double PI = 3.141592653589793;
    const double ALPHA = 0.6931471805599453 / PI;          // -log(0.5)/pi
    const double GAMMA = ALPHA / sqrt(ALPHA * ALPHA + 1.0);
    const double PM = 4.0 / 3.0 * 3.1415 * (0.1 * 0.1 * 0.1) * 2700.0;
    const double ETA = 2.0 * GAMMA * sqrt(6.0e6 * PM);
    const float ETAf  = (float)ETA;
    const float DTPMf = (float)(1e-4 / PM);
    const float GPMf  = (float)(-9.8 * PM);

    cudaFuncSetAttribute(dem_pass, cudaFuncAttributeMaxDynamicSharedMemorySize,
                         SMEM_FLOATS * (int)sizeof(float));

    dim3 grid(32, 128);       // 128/4 y-tiles, 128 z-planes
    dim3 block(256);          // 2 x-cells per thread
    size_t shmem = SMEM_FLOATS * sizeof(float);

    // pass n = 0: neighbors use original velocities of both layers; center = layer 0
    dem_pass<<<grid, block, shmem>>>(
        x, y, z, x + N, y + N, z + N,
        vx, vy, vz, vx + N, vy + N, vz + N,
        x, y, z, vx, vy, vz,
        mask,
        out + 0 * N, out + 2 * N, out + 4 * N,
        ETAf, DTPMf, GPMf);

    // pass n = 1: layer-0 neighbor velocities come from the updated output; center = layer 1
    dem_pass<<<grid, block, shmem>>>(
        x, y, z, x + N, y + N, z + N,
        out + 0 * N, out + 2 * N, out + 4 * N,
        vx + N, vy + N, vz + N,
        x + N, y + N, z + N, vx + N, vy + N, vz + N,
        mask + N,
        out + 1 * N, out + 3 * N, out + 5 * N,
        ETAf, DTPMf, GPMf);
}

// round 17
// speedup vs baseline: 1.2882x; 1.2882x over previous
#include <cuda_runtime.h>
#include <math.h>

#define DD 128
static const int NC = DD * DD * DD;   // cells per layer

// smem: 6 fields x 36 rows (6z x 6y halo) x 128 floats; tile 4y x 4z per CTA
#define F_STRIDE (36 * 128)           // 4608 floats per field
#define SMEM_FLOATS (6 * F_STRIDE)    // 27648 floats = 110592 B
#define FILL_G (6 * 36 * 32)          // float4 granules = 6912

typedef unsigned long long f2;        // packed f32x2

__device__ __forceinline__ f2 pk(float lo, float hi) {
    f2 r; asm("mov.b64 %0,{%1,%2};" : "=l"(r) : "f"(lo), "f"(hi)); return r;
}
__device__ __forceinline__ void up(f2 v, float& lo, float& hi) {
    asm("mov.b64 {%0,%1},%2;" : "=f"(lo), "=f"(hi) : "l"(v));
}
__device__ __forceinline__ f2 fma2(f2 a, f2 b, f2 c) {
    f2 d; asm("fma.rn.f32x2 %0,%1,%2,%3;" : "=l"(d) : "l"(a), "l"(b), "l"(c)); return d;
}
__device__ __forceinline__ f2 mul2(f2 a, f2 b) {
    f2 d; asm("mul.rn.f32x2 %0,%1,%2;" : "=l"(d) : "l"(a), "l"(b)); return d;
}
__device__ __forceinline__ float rsqrt_fast(float x) {
    float y; asm("rsqrt.approx.f32 %0, %1;" : "=f"(y) : "f"(x)); return y;
}

__device__ __forceinline__ float boundary_force(float p, float v, float mv, float ETAf) {
    float lo = (p > 0.1f && p < 0.15f) ? mv : 0.0f;
    float hi = (p > 12.65f) ? mv : 0.0f;
    float fb = 6.0e6f * lo * (0.15f - p);
    fb -= 6.0e6f * hi * (((p - 12.8f) + 0.1f) + 0.05f);
    fb -= ETAf * v * lo;
    fb -= ETAf * v * hi;
    return fb;
}

struct Consts { f2 NEG1, EPS2, KN2, NKPS2, ETA2; };

// One packed interaction: 2 cells (packed centers C[0..5]) vs one window column.
__device__ __forceinline__ void interact(
    const f2* __restrict__ C,
    float wxl, float wxh, float wyl, float wyh, float wzl, float wzh,
    float wvxl, float wvxh, float wvyl, float wvyh, float wvzl, float wvzh,
    f2& FX, f2& FY, f2& FZ, const Consts& K)
{
    f2 dx2 = fma2(pk(wxl, wxh), K.NEG1, C[0]);
    f2 dy2 = fma2(pk(wyl, wyh), K.NEG1, C[1]);
    f2 dz2 = fma2(pk(wzl, wzh), K.NEG1, C[2]);
    f2 s2  = fma2(dz2, dz2, K.EPS2);     // +1e-8 floor folded in
    s2 = fma2(dy2, dy2, s2);
    s2 = fma2(dx2, dx2, s2);
    float s0, s1; up(s2, s0, s1);
    float r0 = rsqrt_fast(s0);
    float r1 = rsqrt_fast(s1);
    r0 = (s0 < 0.01f) ? r0 : 0.0f;       // contact gate folded into r
    r1 = (s1 < 0.01f) ? r1 : 0.0f;
    f2 rg = pk(r0, r1);
    f2 dist2 = mul2(s2, rg);             // = sqrt(s2) where gated-in, else 0
    f2 dvx2 = fma2(pk(wvxl, wvxh), K.NEG1, C[3]);
    f2 dvy2 = fma2(pk(wvyl, wvyh), K.NEG1, C[4]);
    f2 dvz2 = fma2(pk(wvzl, wvzh), K.NEG1, C[5]);
    f2 dot2 = mul2(dvz2, dz2);
    dot2 = fma2(dvy2, dy2, dot2);
    dot2 = fma2(dvx2, dx2, dot2);
    f2 q2 = mul2(dot2, rg);              // dvn/dc (dc clamp automatic: r<=1e4)
    f2 t2 = fma2(K.KN2, dist2, K.NKPS2); // KN*(dist-PS)
    t2 = fma2(K.ETA2, q2, t2);
    f2 coef2 = mul2(t2, rg);             // zero where gated-out
    FX = fma2(coef2, dx2, FX);
    FY = fma2(coef2, dy2, FY);
    FZ = fma2(coef2, dz2, FZ);
}

// window value j (0..5) of field f from quad + shuffle edges
#define WIN(f, j) ((j) == 0 ? s0_[f] : (j) == 1 ? q_[f].x : (j) == 2 ? q_[f].y : \
                   (j) == 3 ? q_[f].z : (j) == 4 ? q_[f].w : s5_[f])

__device__ __forceinline__ void load_centers(
    const float* cx, const float* cy, const float* cz,
    const float* cvx, const float* cvy, const float* cvz,
    int base, f2* C0, f2* C1)
{
    float4 a;
    a = *reinterpret_cast<const float4*>(cx + base);
    C0[0] = pk(a.x, a.y); C1[0] = pk(a.z, a.w);
    a = *reinterpret_cast<const float4*>(cy + base);
    C0[1] = pk(a.x, a.y); C1[1] = pk(a.z, a.w);
    a = *reinterpret_cast<const float4*>(cz + base);
    C0[2] = pk(a.x, a.y); C1[2] = pk(a.z, a.w);
    a = *reinterpret_cast<const float4*>(cvx + base);
    C0[3] = pk(a.x, a.y); C1[3] = pk(a.z, a.w);
    a = *reinterpret_cast<const float4*>(cvy + base);
    C0[4] = pk(a.x, a.y); C1[4] = pk(a.z, a.w);
    a = *reinterpret_cast<const float4*>(cvz + base);
    C0[5] = pk(a.x, a.y); C1[5] = pk(a.z, a.w);
}

__device__ __forceinline__ void epilogue_store(
    const f2* C0, const f2* C1, f2 FX0, f2 FY0, f2 FZ0, f2 FX1, f2 FY1, f2 FZ1,
    const float* cmask, float* ovx, float* ovy, float* ovz, int base,
    float ETAf, float DTPMf, float GPMf)
{
    float fxa[4], fya[4], fza[4];
    up(FX0, fxa[0], fxa[1]); up(FX1, fxa[2], fxa[3]);
    up(FY0, fya[0], fya[1]); up(FY1, fya[2], fya[3]);
    up(FZ0, fza[0], fza[1]); up(FZ1, fza[2], fza[3]);

    float xn[4], yn[4], zn[4], vxn[4], vyn[4], vzn[4];
    up(C0[0], xn[0], xn[1]);  up(C1[0], xn[2], xn[3]);
    up(C0[1], yn[0], yn[1]);  up(C1[1], yn[2], yn[3]);
    up(C0[2], zn[0], zn[1]);  up(C1[2], zn[2], zn[3]);
    up(C0[3], vxn[0], vxn[1]); up(C1[3], vxn[2], vxn[3]);
    up(C0[4], vyn[0], vyn[1]); up(C1[4], vyn[2], vyn[3]);
    up(C0[5], vzn[0], vzn[1]); up(C1[5], vzn[2], vzn[3]);

    float4 mk4 = *reinterpret_cast<const float4*>(cmask + base);
    const float mk[4] = {mk4.x, mk4.y, mk4.z, mk4.w};

    float outx[4], outy[4], outz[4];
#pragma unroll
    for (int c = 0; c < 4; ++c) {
        float mv = mk[c];
        float fxb = boundary_force(xn[c], vxn[c], mv, ETAf);
        float fyb = boundary_force(yn[c], vyn[c], mv, ETAf);
        float fzb = boundary_force(zn[c], vzn[c], mv, ETAf);
        float sc = DTPMf * mv;
        outx[c] = vxn[c] + sc * (fxb - fxa[c]);
        outy[c] = vyn[c] + sc * (fyb - fya[c]);
        outz[c] = vzn[c] + sc * ((GPMf - fza[c]) + fzb);
    }
    *reinterpret_cast<float4*>(ovx + base) = make_float4(outx[0], outx[1], outx[2], outx[3]);
    *reinterpret_cast<float4*>(ovy + base) = make_float4(outy[0], outy[1], outy[2], outy[3]);
    *reinterpret_cast<float4*>(ovz + base) = make_float4(outz[0], outz[1], outz[2], outz[3]);
}

__global__ void __launch_bounds__(256, 2)
dem_pass(const float* __restrict__ x0, const float* __restrict__ y0, const float* __restrict__ z0,
         const float* __restrict__ x1, const float* __restrict__ y1, const float* __restrict__ z1,
         const float* __restrict__ vxl0, const float* __restrict__ vyl0, const float* __restrict__ vzl0,
         const float* __restrict__ vxl1, const float* __restrict__ vyl1, const float* __restrict__ vzl1,
         const float* __restrict__ cx, const float* __restrict__ cy, const float* __restrict__ cz,
         const float* __restrict__ cvx, const float* __restrict__ cvy, const float* __restrict__ cvz,
         const float* __restrict__ cmask,
         float* __restrict__ ovx, float* __restrict__ ovy, float* __restrict__ ovz,
         float ETAf, float DTPMf, float GPMf)
{
    extern __shared__ float sm[];

    const int lane = threadIdx.x;                    // 0..31, x-quads
    const int ty = threadIdx.y;                      // 0..3
    const int tz = threadIdx.z;                      // 0..1 (each handles 2 z)
    const int tid = (tz * 4 + ty) * 32 + lane;       // 0..255
    const int by0 = blockIdx.x * 4;                  // y tile base
    const int bz0 = blockIdx.y * 4;                  // z tile base
    const int zA = bz0 + 2 * tz;                     // first z-cell
    const int baseA = (zA * DD + (by0 + ty)) * DD + lane * 4;
    const int baseB = baseA + DD * DD;               // z+1

    Consts K;
    K.NEG1  = pk(-1.0f, -1.0f);
    K.EPS2  = pk(1e-8f, 1e-8f);
    K.KN2   = pk(6.0e6f, 6.0e6f);
    K.NKPS2 = pk(-600000.0f, -600000.0f);
    K.ETA2  = pk(ETAf, ETAf);

    // centers for both z-cells (packed pairs)
    f2 CA0[6], CA1[6], CB0[6], CB1[6];
    load_centers(cx, cy, cz, cvx, cvy, cvz, baseA, CA0, CA1);
    load_centers(cx, cy, cz, cvx, cvy, cvz, baseB, CB0, CB1);

    f2 AX0 = 0, AY0 = 0, AZ0 = 0, AX1 = 0, AY1 = 0, AZ1 = 0;  // cell A accums
    f2 BX0 = 0, BY0 = 0, BZ0 = 0, BX1 = 0, BY1 = 0, BZ1 = 0;  // cell B accums

#pragma unroll
    for (int m = 0; m < 2; ++m) {
        const float* Ps[6];
        Ps[0] = m ? x1 : x0;   Ps[1] = m ? y1 : y0;   Ps[2] = m ? z1 : z0;
        Ps[3] = m ? vxl1 : vxl0; Ps[4] = m ? vyl1 : vyl0; Ps[5] = m ? vzl1 : vzl0;

        if (m) __syncthreads();   // protect previous phase's reads before overwrite

        // cooperative tile load: 36 rows (6z x 6y) of 128 floats per field
        for (int g = tid; g < FILL_G; g += 256) {
            int f = g / 1152, rem = g - f * 1152;
            int r = rem >> 5, l = rem & 31;
            int gz = (bz0 + r / 6 - 1) & 127;
            int gy = (by0 + r % 6 - 1) & 127;
            *reinterpret_cast<float4*>(sm + f * F_STRIDE + r * 128 + l * 4) =
                *reinterpret_cast<const float4*>(Ps[f] + (gz * DD + gy) * DD + l * 4);
        }
        __syncthreads();

        // 3 dy x 4 z-rows; shared rows serve both z-cells
#pragma unroll
        for (int dy = 0; dy < 3; ++dy) {
#pragma unroll
            for (int k = 0; k < 4; ++k) {
                const int zl = 2 * tz + k;           // local z row (0..5)
                const int roff = (zl * 6 + (ty + dy)) * 128 + lane * 4;
                float4 q_[6];
                float s0_[6], s5_[6];
#pragma unroll
                for (int f = 0; f < 6; ++f) {
                    q_[f] = *reinterpret_cast<const float4*>(sm + f * F_STRIDE + roff);
                    // circular warp shuffle = periodic x wrap (warp covers full x axis)
                    s0_[f] = __shfl_sync(0xffffffffu, q_[f].w, (lane + 31) & 31);
                    s5_[f] = __shfl_sync(0xffffffffu, q_[f].x, (lane + 1) & 31);
                }
                if (k < 3) {   // rows zl = 2tz..2tz+2 serve cell A (dz -1..1)
#pragma unroll
                    for (int j = 0; j < 3; ++j) {
                        interact(CA0,
                                 WIN(0, j), WIN(0, j + 1), WIN(1, j), WIN(1, j + 1),
                                 WIN(2, j), WIN(2, j + 1), WIN(3, j), WIN(3, j + 1),
                                 WIN(4, j), WIN(4, j + 1), WIN(5, j), WIN(5, j + 1),
                                 AX0, AY0, AZ0, K);
                        interact(CA1,
                                 WIN(0, j + 2), WIN(0, j + 3), WIN(1, j + 2), WIN(1, j + 3),
                                 WIN(2, j + 2), WIN(2, j + 3), WIN(3, j + 2), WIN(3, j + 3),
                                 WIN(4, j + 2), WIN(4, j + 3), WIN(5, j + 2), WIN(5, j + 3),
                                 AX1, AY1, AZ1, K);
                    }
                }
                if (k > 0) {   // rows zl = 2tz+1..2tz+3 serve cell B (dz -1..1)
#pragma unroll
                    for (int j = 0; j < 3; ++j) {
                        interact(CB0,
                                 WIN(0, j), WIN(0, j + 1), WIN(1, j), WIN(1, j + 1),
                                 WIN(2, j), WIN(2, j + 1), WIN(3, j), WIN(3, j + 1),
                                 WIN(4, j), WIN(4, j + 1), WIN(5, j), WIN(5, j + 1),
                                 BX0, BY0, BZ0, K);
                        interact(CB1,
                                 WIN(0, j + 2), WIN(0, j + 3), WIN(1, j + 2), WIN(1, j + 3),
                                 WIN(2, j + 2), WIN(2, j + 3), WIN(3, j + 2), WIN(3, j + 3),
                                 WIN(4, j + 2), WIN(4, j + 3), WIN(5, j + 2), WIN(5, j + 3),
                                 BX1, BY1, BZ1, K);
                    }
                }
            }
        }
    }

    epilogue_store(CA0, CA1, AX0, AY0, AZ0, AX1, AY1, AZ1,
                   cmask, ovx, ovy, ovz, baseA, ETAf, DTPMf, GPMf);
    epilogue_store(CB0, CB1, BX0, BY0, BZ0, BX1, BY1, BZ1,
                   cmask, ovx, ovy, ovz, baseB, ETAf, DTPMf, GPMf);
}

extern "C" void kernel_launch(void* const* d_in, const int* in_sizes, int n_in,
                              void* d_out, int out_size)
{
    const float* x  = (const float*)d_in[0];
    const float* y  = (const float*)d_in[1];
    const float* z  = (const float*)d_in[2];
    const float* vx = (const float*)d_in[3];
    const float* vy = (const float*)d_in[4];
    const float* vz = (const float*)d_in[5];
    const float* mask = (const float*)d_in[6];
    float* out = (float*)d_out;
    const int N = NC;

    const double PI = 3.141592653589793;
    const double ALPHA = 0.6931471805599453 / PI;          // -log(0.5)/pi
    const double GAMMA = ALPHA / sqrt(ALPHA * ALPHA + 1.0);
    const double PM = 4.0 / 3.0 * 3.1415 * (0.1 * 0.1 * 0.1) * 2700.0;
    const double ETA = 2.0 * GAMMA * sqrt(6.0e6 * PM);
    const float ETAf  = (float)ETA;
    const float DTPMf = (float)(1e-4 / PM);
    const float GPMf  = (float)(-9.8 * PM);

    cudaFuncSetAttribute(dem_pass, cudaFuncAttributeMaxDynamicSharedMemorySize,
                         SMEM_FLOATS * (int)sizeof(float));

    dim3 grid(32, 32);        // 128/4 y-tiles, 128/4 z-tiles
    dim3 block(32, 4, 2);     // 256 threads; each does 4x * 2z cells
    size_t shmem = SMEM_FLOATS * sizeof(float);

    // pass n = 0: neighbors use original velocities of both layers
    dem_pass<<<grid, block, shmem>>>(
        x, y, z, x + N, y + N, z + N,
        vx, vy, vz, vx + N, vy + N, vz + N,
        x, y, z, vx, vy, vz,
        mask,
        out + 0 * N, out + 2 * N, out + 4 * N,
        ETAf, DTPMf, GPMf);

    // pass n = 1: layer-0 neighbor velocities come from updated output
    dem_pass<<<grid, block, shmem>>>(
        x, y, z, x + N, y + N, z + N,
        out + 0 * N, out + 2 * N, out + 4 * N,
        vx + N, vy + N, vz + N,
        x + N, y + N, z + N, vx + N, vy + N, vz + N,
        mask + N,
        out + 1 * N, out + 3 * N, out + 5 * N,
        ETAf, DTPMf, GPMf);
}